// round 7
// baseline (speedup 1.0000x reference)
#include <cuda_runtime.h>

// IF spiking neuron forward, T=4. R7: identical to R6 (batch-fastest grid,
// thread per (feature-float4, batch), front-batched loads, plain LDG/STG,
// 32 regs) but with 128-thread blocks. 4096 regs/block gives the RF
// allocator finer granularity -> closer to 64 resident warps/SM (R6's
// 256-thr blocks quantized to ~52-56 warps). L2 param sharing preserved:
// 16 consecutive blocks now cover all 8 batches of each 2KB feature window.

#ifndef T_STEPS
#define T_STEPS 4
#endif

__global__ __launch_bounds__(128) void if_fwd_kernel(
    const float4* __restrict__ x,      // [T, B, N4]
    const float4* __restrict__ thre,   // [N4]
    const float4* __restrict__ dtm,    // [N4]
    float4* __restrict__ out,          // [T, B, N4]
    long long N4,
    int B)
{
    long long f = (long long)blockIdx.y * blockDim.x + threadIdx.x;
    if (f >= N4) return;
    const int b = blockIdx.x;   // batch fastest-varying -> L2 param sharing

    const float4 th = thre[f];
    float4 mem = dtm[f];
    mem.x *= th.x; mem.y *= th.y; mem.z *= th.z; mem.w *= th.w;

    const long long tstride = (long long)B * N4;
    const float4* xp = x + (long long)b * N4 + f;
    float4* op = out + (long long)b * N4 + f;

    // Front-batch the 4 independent loads (MLP=4).
    float4 xv0 = xp[0 * tstride];
    float4 xv1 = xp[1 * tstride];
    float4 xv2 = xp[2 * tstride];
    float4 xv3 = xp[3 * tstride];

    float4 s;

    // t = 0
    mem.x += xv0.x; mem.y += xv0.y; mem.z += xv0.z; mem.w += xv0.w;
    s.x = (mem.x >= th.x) ? th.x : 0.0f;
    s.y = (mem.y >= th.y) ? th.y : 0.0f;
    s.z = (mem.z >= th.z) ? th.z : 0.0f;
    s.w = (mem.w >= th.w) ? th.w : 0.0f;
    op[0 * tstride] = s;
    mem.x -= s.x; mem.y -= s.y; mem.z -= s.z; mem.w -= s.w;

    // t = 1
    mem.x += xv1.x; mem.y += xv1.y; mem.z += xv1.z; mem.w += xv1.w;
    s.x = (mem.x >= th.x) ? th.x : 0.0f;
    s.y = (mem.y >= th.y) ? th.y : 0.0f;
    s.z = (mem.z >= th.z) ? th.z : 0.0f;
    s.w = (mem.w >= th.w) ? th.w : 0.0f;
    op[1 * tstride] = s;
    mem.x -= s.x; mem.y -= s.y; mem.z -= s.z; mem.w -= s.w;

    // t = 2
    mem.x += xv2.x; mem.y += xv2.y; mem.z += xv2.z; mem.w += xv2.w;
    s.x = (mem.x >= th.x) ? th.x : 0.0f;
    s.y = (mem.y >= th.y) ? th.y : 0.0f;
    s.z = (mem.z >= th.z) ? th.z : 0.0f;
    s.w = (mem.w >= th.w) ? th.w : 0.0f;
    op[2 * tstride] = s;
    mem.x -= s.x; mem.y -= s.y; mem.z -= s.z; mem.w -= s.w;

    // t = 3 (no trailing mem update needed)
    mem.x += xv3.x; mem.y += xv3.y; mem.z += xv3.z; mem.w += xv3.w;
    s.x = (mem.x >= th.x) ? th.x : 0.0f;
    s.y = (mem.y >= th.y) ? th.y : 0.0f;
    s.z = (mem.z >= th.z) ? th.z : 0.0f;
    s.w = (mem.w >= th.w) ? th.w : 0.0f;
    op[3 * tstride] = s;
}

extern "C" void kernel_launch(void* const* d_in, const int* in_sizes, int n_in,
                              void* d_out, int out_size)
{
    const float* x   = (const float*)d_in[0];
    const float* th  = (const float*)d_in[1];
    const float* dtm = (const float*)d_in[2];
    float* out = (float*)d_out;

    const long long N = in_sizes[1];                   // 1024*3072
    const int B = (int)(in_sizes[0] / (T_STEPS * N));  // 8
    const long long N4 = N / 4;

    const int threads = 128;
    dim3 grid((unsigned)B, (unsigned)((N4 + threads - 1) / threads));

    if_fwd_kernel<<<grid, threads>>>(
        (const float4*)x, (const float4*)th, (const float4*)dtm,
        (float4*)out, N4, B);
}